// round 14
// baseline (speedup 1.0000x reference)
#include <cuda_runtime.h>
#include <cuda_fp16.h>
#include <math.h>
#include <stdint.h>
#include <stddef.h>

// Problem constants
#define Bb 2
#define Ss 4096
#define Hh 1024
#define NKH 8
#define NVH 16
#define DK 64
#define DV 64
#define KEY_DIM 512
#define VAL_DIM 1024
#define CONV_DIM 2048
#define KSZ 4
#define MROWS (Bb*Ss)        // 8192

// ------------------------- scratch (static device memory) -------------------
__device__ float g_mixed[(size_t)Bb*Ss*CONV_DIM];
__device__ float g_conv [(size_t)Bb*Ss*CONV_DIM];
__device__ float g_z    [(size_t)Bb*Ss*VAL_DIM];
__device__ float g_g    [(size_t)Bb*Ss*NVH];
__device__ float g_beta [(size_t)Bb*Ss*NVH];
__device__ float g_o    [(size_t)Bb*Ss*VAL_DIM];

// fp16 operands
__device__ __half g_hs_h  [(size_t)MROWS*Hh];
__device__ __half g_wqkv_h[(size_t)CONV_DIM*Hh];
__device__ __half g_wz_h  [(size_t)VAL_DIM*Hh];
__device__ __half g_wo_h  [(size_t)Hh*VAL_DIM];
__device__ __half g_h_h   [(size_t)MROWS*VAL_DIM];

// ========================= helpers ==========================================
__device__ __forceinline__ uint32_t smem_u32(const void* p) {
    uint32_t a;
    asm("{ .reg .u64 t; cvta.to.shared.u64 t, %1; cvt.u32.u64 %0, t; }"
        : "=r"(a) : "l"(p));
    return a;
}

#define LDSM4(r0, r1, r2, r3, addr) \
    asm volatile("ldmatrix.sync.aligned.m8n8.x4.shared.b16 {%0,%1,%2,%3}, [%4];" \
                 : "=r"(r0), "=r"(r1), "=r"(r2), "=r"(r3) : "r"(addr))

#define MMA16816(d, a, b0, b1) \
    asm volatile("mma.sync.aligned.m16n8k16.row.col.f32.f16.f16.f32 " \
                 "{%0,%1,%2,%3},{%4,%5,%6,%7},{%8,%9},{%0,%1,%2,%3};" \
                 : "+f"((d)[0]), "+f"((d)[1]), "+f"((d)[2]), "+f"((d)[3]) \
                 : "r"((a)[0]), "r"((a)[1]), "r"((a)[2]), "r"((a)[3]), \
                   "r"(b0), "r"(b1))

#define CP_ASYNC16(dst, src) \
    asm volatile("cp.async.cg.shared.global [%0], [%1], 16;" \
                 :: "r"(dst), "l"(src))
#define CP_ASYNC4(dst, src) \
    asm volatile("cp.async.ca.shared.global [%0], [%1], 4;" \
                 :: "r"(dst), "l"(src))
#define CP_COMMIT() asm volatile("cp.async.commit_group;" ::: "memory")
#define CP_WAIT1()  asm volatile("cp.async.wait_group 1;" ::: "memory")

// ------------------ fp32 -> fp16 (elementwise) ------------------------------
__global__ __launch_bounds__(256) void cvt_fp16(const float* __restrict__ x,
                                                __half* __restrict__ hi,
                                                int n4) {
    int i = blockIdx.x * blockDim.x + threadIdx.x;
    if (i >= n4) return;
    float4 v = ((const float4*)x)[i];
    __half2 p0 = __floats2half2_rn(v.x, v.y);
    __half2 p1 = __floats2half2_rn(v.z, v.w);
    ((uint2*)hi)[i] = make_uint2(*(uint32_t*)&p0, *(uint32_t*)&p1);
}

// ===================== fp16 HMMA GEMM: C = A * B^T ==========================
// K=64 per stage (half the stage count -> half the per-stage overhead).
// 128B rows, XOR swizzle chunk^=row&7 (conflict-free ldmatrix + STS).
// 3-stage cp.async ring, 96KB smem, 2 CTAs/SM.
#define ARR_B 16384                        // 128 rows x 128B
#define STG_BYTES (2 * ARR_B)              // 32768: A, B
#define GEMM_SMEM (3 * STG_BYTES)          // 98304

__global__ __launch_bounds__(256, 2) void hmma_gemm_half(
        const __half* __restrict__ A, const __half* __restrict__ B,
        float* __restrict__ C, int M, int N, int K) {
    extern __shared__ char dynsmem[];
    const uint32_t sbase = smem_u32(dynsmem);

    const int tid  = threadIdx.x;
    const int lane = tid & 31;
    const int wid  = tid >> 5;
    const int wm   = wid & 3;
    const int wn   = wid >> 2;
    const int brow = blockIdx.y * 128;
    const int bcol = blockIdx.x * 128;

    const uint32_t aRow = (uint32_t)(wm * 32 + (lane & 15));
    const uint32_t aKq  = (uint32_t)(lane >> 4);           // 0/1 within a K16
    const uint32_t bRow = (uint32_t)(wn * 64 + (lane & 7) + ((lane >> 4) << 3));
    const uint32_t bKq  = (uint32_t)((lane >> 3) & 1);

    float acc[2][8][4];
#pragma unroll
    for (int i = 0; i < 2; i++)
#pragma unroll
        for (int j = 0; j < 8; j++)
#pragma unroll
            for (int c = 0; c < 4; c++) acc[i][j][c] = 0.f;

    const int NK = K / 64;

// 4096 16B segments per stage (A+B); 8 per thread.
// arr = j>>2, idx = tid + (j&3)*256: row = idx>>3, chunk = idx&7.
#define ISSUE_STAGE(s) do { \
    uint32_t buf = sbase + (uint32_t)(((s) % 3) * STG_BYTES); \
    int k0 = (s) * 64; \
    _Pragma("unroll") \
    for (int j = 0; j < 8; j++) { \
        const int arr = j >> 2; \
        int idx = tid + (j & 3) * 256; \
        int row = idx >> 3; \
        int chunk = idx & 7; \
        uint32_t sw = (uint32_t)((row << 7) + ((chunk ^ (row & 7)) << 4)); \
        size_t so = (size_t)(((arr == 0) ? brow : bcol) + row) * K + k0 + chunk * 8; \
        const __half* src = (arr == 0) ? A : B; \
        CP_ASYNC16(buf + arr * ARR_B + sw, src + so); \
    } \
    CP_COMMIT(); \
} while (0)

    ISSUE_STAGE(0);
    ISSUE_STAGE(1);

    for (int s = 0; s < NK; s++) {
        CP_WAIT1();                 // stage s resident
        __syncthreads();
        if (s + 2 < NK) ISSUE_STAGE(s + 2);
        else CP_COMMIT();           // uniform group accounting

        const uint32_t stg = sbase + (uint32_t)((s % 3) * STG_BYTES);
#pragma unroll
        for (int kh = 0; kh < 4; kh++) {
            const uint32_t kqb = (uint32_t)(kh * 2);
            uint32_t ah[2][4], bh[8][2];
#pragma unroll
            for (int mi = 0; mi < 2; mi++) {
                uint32_t r  = aRow + mi * 16;
                uint32_t qq = aKq + kqb;
                uint32_t ad = stg + (r << 7) + ((qq ^ (r & 7)) << 4);
                LDSM4(ah[mi][0], ah[mi][1], ah[mi][2], ah[mi][3], ad);
            }
#pragma unroll
            for (int g = 0; g < 4; g++) {
                uint32_t r  = bRow + g * 16;
                uint32_t qq = bKq + kqb;
                uint32_t bd = stg + ARR_B + (r << 7) + ((qq ^ (r & 7)) << 4);
                LDSM4(bh[g*2][0], bh[g*2][1], bh[g*2+1][0], bh[g*2+1][1], bd);
            }
#pragma unroll
            for (int mi = 0; mi < 2; mi++)
#pragma unroll
                for (int nf = 0; nf < 8; nf++)
                    MMA16816(acc[mi][nf], ah[mi], bh[nf][0], bh[nf][1]);
        }
    }

#pragma unroll
    for (int mi = 0; mi < 2; mi++) {
        int r0 = brow + wm * 32 + mi * 16 + (lane >> 2);
#pragma unroll
        for (int nf = 0; nf < 8; nf++) {
            int c = bcol + wn * 64 + nf * 8 + (lane & 3) * 2;
            *(float2*)&C[(size_t)r0 * N + c] =
                make_float2(acc[mi][nf][0], acc[mi][nf][1]);
            *(float2*)&C[(size_t)(r0 + 8) * N + c] =
                make_float2(acc[mi][nf][2], acc[mi][nf][3]);
        }
    }
#undef ISSUE_STAGE
}

// ------------------- beta / g projections (N=32 skinny GEMM) ----------------
__global__ __launch_bounds__(256) void proj_ab(const float* __restrict__ hs,
                                               const float* __restrict__ Wb,
                                               const float* __restrict__ Wa,
                                               const float* __restrict__ dt_bias,
                                               const float* __restrict__ A_log,
                                               float* __restrict__ gout,
                                               float* __restrict__ bout) {
    __shared__ float As[64][32];
    __shared__ float Ws[32][32];
    const int tid = threadIdx.x;
    const int row0 = blockIdx.x * 64;
    const int ty = tid >> 5;
    const int tx = tid & 31;

    float acc[8];
#pragma unroll
    for (int i = 0; i < 8; i++) acc[i] = 0.f;

    const int ar = tid >> 2;
    const int ak = (tid & 3) * 8;

    for (int k0 = 0; k0 < Hh; k0 += 32) {
        float4 a0 = *(const float4*)(hs + (size_t)(row0 + ar) * Hh + k0 + ak);
        float4 a1 = *(const float4*)(hs + (size_t)(row0 + ar) * Hh + k0 + ak + 4);
        As[ar][ak + 0] = a0.x; As[ar][ak + 1] = a0.y; As[ar][ak + 2] = a0.z; As[ar][ak + 3] = a0.w;
        As[ar][ak + 4] = a1.x; As[ar][ak + 5] = a1.y; As[ar][ak + 6] = a1.z; As[ar][ak + 7] = a1.w;
#pragma unroll
        for (int i = tid; i < 1024; i += 256) {
            int n = i >> 5, kk = i & 31;
            float w = (n < 16) ? Wb[(size_t)n * Hh + k0 + kk]
                               : Wa[(size_t)(n - 16) * Hh + k0 + kk];
            Ws[kk][n] = w;
        }
        __syncthreads();
#pragma unroll
        for (int kk = 0; kk < 32; kk++) {
            float w = Ws[kk][tx];
#pragma unroll
            for (int i = 0; i < 8; i++) acc[i] += As[ty * 8 + i][kk] * w;
        }
        __syncthreads();
    }

    if (tx < 16) {
#pragma unroll
        for (int i = 0; i < 8; i++) {
            int row = row0 + ty * 8 + i;
            bout[(size_t)row * NVH + tx] = 1.f / (1.f + expf(-acc[i]));
        }
    } else {
        int hh = tx - 16;
        float al = expf(A_log[hh]);
        float db = dt_bias[hh];
#pragma unroll
        for (int i = 0; i < 8; i++) {
            int row = row0 + ty * 8 + i;
            float x = acc[i] + db;
            float sp = (x > 20.f) ? x : log1pf(expf(x));
            gout[(size_t)row * NVH + hh] = -al * sp;
        }
    }
}

// ------------------------- depthwise causal conv + silu ---------------------
__global__ __launch_bounds__(256) void conv_silu(const float* __restrict__ x,
                                                 const float* __restrict__ w,
                                                 float* __restrict__ y) {
    const int C4 = CONV_DIM / 4;
    int idx = blockIdx.x * blockDim.x + threadIdx.x;
    int c4 = idx & (C4 - 1);
    int s  = (idx >> 9) & (Ss - 1);
    int b  = idx >> 21;

    float4 t0 = ((const float4*)w)[c4 * 4 + 0];
    float4 t1 = ((const float4*)w)[c4 * 4 + 1];
    float4 t2 = ((const float4*)w)[c4 * 4 + 2];
    float4 t3 = ((const float4*)w)[c4 * 4 + 3];

    float a0 = 0.f, a1 = 0.f, a2 = 0.f, a3 = 0.f;
#pragma unroll
    for (int j = 0; j < KSZ; j++) {
        int st = s - (KSZ - 1) + j;
        if (st < 0) continue;
        float4 xv = ((const float4*)x)[((size_t)b * Ss + st) * C4 + c4];
        float w0 = (j == 0) ? t0.x : (j == 1) ? t0.y : (j == 2) ? t0.z : t0.w;
        float w1 = (j == 0) ? t1.x : (j == 1) ? t1.y : (j == 2) ? t1.z : t1.w;
        float w2 = (j == 0) ? t2.x : (j == 1) ? t2.y : (j == 2) ? t2.z : t2.w;
        float w3 = (j == 0) ? t3.x : (j == 1) ? t3.y : (j == 2) ? t3.z : t3.w;
        a0 += w0 * xv.x; a1 += w1 * xv.y; a2 += w2 * xv.z; a3 += w3 * xv.w;
    }
    float4 out;
    out.x = a0 / (1.f + expf(-a0));
    out.y = a1 / (1.f + expf(-a1));
    out.z = a2 / (1.f + expf(-a2));
    out.w = a3 / (1.f + expf(-a3));
    ((float4*)y)[((size_t)b * Ss + s) * C4 + c4] = out;
}

// ------------------------- gated delta-rule recurrence ----------------------
// Exact R10 structure (256 thr, 4-lane k split, inline o store).
#define CHNK 32
#define SCAN_TFLOATS (3*CHNK*64 + 2*CHNK)
#define SCAN_SMEM (2*SCAN_TFLOATS*4)

__global__ __launch_bounds__(256) void delta_scan(const float* __restrict__ conv,
                                                  const float* __restrict__ gg,
                                                  const float* __restrict__ bb_,
                                                  float* __restrict__ out) {
    extern __shared__ float ss[];

    const int tid  = threadIdx.x;
    const int lane = tid & 31;
    const int warp = tid >> 5;
    const int b = blockIdx.x >> 4;
    const int h = blockIdx.x & 15;

    const int v  = warp * 8 + (lane >> 2);
    const int kb = (lane & 3) * 16;

    const int qoff = (h >> 1) * DK;
    const int koff = KEY_DIM + (h >> 1) * DK;
    const int voff = 2 * KEY_DIM + h * DV;
    const int offs[3] = {qoff, koff, voff};

    float S0r[8], S1r[8];
#pragma unroll
    for (int i = 0; i < 8; i++) { S0r[i] = 0.f; S1r[i] = 0.f; }

#define ISSUE_CHUNK(cbase, dstf) do { \
    float* _d = (dstf); \
    for (int i = tid; i < CHNK * 48; i += 256) { \
        int t = i / 48; int r = i - t * 48; int tensor = r >> 4; int seg = r & 15; \
        size_t row = ((size_t)b * Ss + (cbase) + t) * CONV_DIM; \
        CP_ASYNC16(smem_u32(_d + tensor * (CHNK*64) + t * 64 + seg * 4), \
                   conv + row + offs[tensor] + seg * 4); \
    } \
    if (tid < CHNK) { \
        size_t r = ((size_t)b * Ss + (cbase) + tid) * NVH + h; \
        CP_ASYNC4(smem_u32(_d + 3*CHNK*64 + tid), gg + r); \
        CP_ASYNC4(smem_u32(_d + 3*CHNK*64 + CHNK + tid), bb_ + r); \
    } \
    CP_COMMIT(); \
} while (0)

    ISSUE_CHUNK(0, ss);

    const int NC = Ss / CHNK;
    for (int c = 0; c < NC; c++) {
        const int p = c & 1;
        __syncthreads();
        if (c + 1 < NC) ISSUE_CHUNK((c + 1) * CHNK, ss + (p ^ 1) * SCAN_TFLOATS);
        else CP_COMMIT();
        CP_WAIT1();
        __syncthreads();

        const float* tq = ss + p * SCAN_TFLOATS;
        const float* tk = tq + CHNK * 64;
        const float* tv = tk + CHNK * 64;
        const float* tg = tv + CHNK * 64;
        const float* tb = tg + CHNK;

        for (int t = 0; t < CHNK; t++) {
            float4 k0 = *(const float4*)(tk + t * 64 + kb + 0);
            float4 k1 = *(const float4*)(tk + t * 64 + kb + 4);
            float4 k2 = *(const float4*)(tk + t * 64 + kb + 8);
            float4 k3 = *(const float4*)(tk + t * 64 + kb + 12);
            float4 q0 = *(const float4*)(tq + t * 64 + kb + 0);
            float4 q1 = *(const float4*)(tq + t * 64 + kb + 4);
            float4 q2 = *(const float4*)(tq + t * 64 + kb + 8);
            float4 q3 = *(const float4*)(tq + t * 64 + kb + 12);
            float vt  = tv[t * 64 + v];
            float dec = __expf(tg[t]);
            float bt  = tb[t];

            float kr[16] = {k0.x,k0.y,k0.z,k0.w, k1.x,k1.y,k1.z,k1.w,
                            k2.x,k2.y,k2.z,k2.w, k3.x,k3.y,k3.z,k3.w};
            float qr[16] = {q0.x,q0.y,q0.z,q0.w, q1.x,q1.y,q1.z,q1.w,
                            q2.x,q2.y,q2.z,q2.w, q3.x,q3.y,q3.z,q3.w};

            float a0 = 0.f, a1 = 0.f, a2 = 0.f, a3 = 0.f;
#pragma unroll
            for (int i = 0; i < 4; i++) {
                S0r[i]     *= dec;  a0 += S0r[i]     * kr[i];
                S0r[i + 4] *= dec;  a1 += S0r[i + 4] * kr[i + 4];
                S1r[i]     *= dec;  a2 += S1r[i]     * kr[i + 8];
                S1r[i + 4] *= dec;  a3 += S1r[i + 4] * kr[i + 12];
            }
            float kv = (a0 + a1) + (a2 + a3);
            kv += __shfl_xor_sync(0xffffffffu, kv, 1);
            kv += __shfl_xor_sync(0xffffffffu, kv, 2);
            float delta = (vt - kv) * bt;

            float o0 = 0.f, o1 = 0.f, o2 = 0.f, o3 = 0.f;
#pragma unroll
            for (int i = 0; i < 4; i++) {
                S0r[i]     += kr[i]      * delta;  o0 += S0r[i]     * qr[i];
                S0r[i + 4] += kr[i + 4]  * delta;  o1 += S0r[i + 4] * qr[i + 4];
                S1r[i]     += kr[i + 8]  * delta;  o2 += S1r[i]     * qr[i + 8];
                S1r[i + 4] += kr[i + 12] * delta;  o3 += S1r[i + 4] * qr[i + 12];
            }
            float o = (o0 + o1) + (o2 + o3);
            o += __shfl_xor_sync(0xffffffffu, o, 1);
            o += __shfl_xor_sync(0xffffffffu, o, 2);
            if ((lane & 3) == 0)
                out[(((size_t)b * Ss + c * CHNK + t) * NVH + h) * DV + v] = o * 0.125f;
        }
    }
#undef ISSUE_CHUNK
}

// -------------- gated RMSNorm (emits fp16 directly) -------------------------
__global__ __launch_bounds__(256) void gate_norm(const float* __restrict__ o,
                                                 const float* __restrict__ z,
                                                 const float* __restrict__ w,
                                                 __half* __restrict__ hh) {
    int gid  = blockIdx.x * 8 + (threadIdx.x >> 5);
    int lane = threadIdx.x & 31;
    size_t base = (size_t)gid * 64;
    float z0 = z[base + lane],      z1 = z[base + lane + 32];
    float o0 = o[base + lane],      o1 = o[base + lane + 32];
    float v0 = o0 * (z0 / (1.f + expf(-z0)));
    float v1 = o1 * (z1 / (1.f + expf(-z1)));
    float ss = v0 * v0 + v1 * v1;
#pragma unroll
    for (int m = 16; m; m >>= 1) ss += __shfl_xor_sync(0xffffffffu, ss, m);
    float scale = rsqrtf(ss * (1.f / 64.f) + 1e-6f);
    hh[base + lane]      = __float2half_rn(v0 * scale * w[lane]);
    hh[base + lane + 32] = __float2half_rn(v1 * scale * w[lane + 32]);
}

// ------------------------- launcher -----------------------------------------
extern "C" void kernel_launch(void* const* d_in, const int* in_sizes, int n_in,
                              void* d_out, int out_size) {
    const float* hs       = (const float*)d_in[0];
    const float* W_qkv    = (const float*)d_in[1];
    const float* conv_w   = (const float*)d_in[2];
    const float* W_z      = (const float*)d_in[3];
    const float* W_b      = (const float*)d_in[4];
    const float* W_a      = (const float*)d_in[5];
    const float* dt_bias  = (const float*)d_in[6];
    const float* A_log    = (const float*)d_in[7];
    const float* norm_w   = (const float*)d_in[8];
    const float* W_out    = (const float*)d_in[9];
    float* out = (float*)d_out;

    float *p_mixed, *p_conv, *p_z, *p_g, *p_beta, *p_o;
    __half *hs_h, *wq_h, *wz_h, *wo_h, *h_h;
    cudaGetSymbolAddress((void**)&p_mixed, g_mixed);
    cudaGetSymbolAddress((void**)&p_conv,  g_conv);
    cudaGetSymbolAddress((void**)&p_z,     g_z);
    cudaGetSymbolAddress((void**)&p_g,     g_g);
    cudaGetSymbolAddress((void**)&p_beta,  g_beta);
    cudaGetSymbolAddress((void**)&p_o,     g_o);
    cudaGetSymbolAddress((void**)&hs_h,    g_hs_h);
    cudaGetSymbolAddress((void**)&wq_h,    g_wqkv_h);
    cudaGetSymbolAddress((void**)&wz_h,    g_wz_h);
    cudaGetSymbolAddress((void**)&wo_h,    g_wo_h);
    cudaGetSymbolAddress((void**)&h_h,     g_h_h);

    cudaFuncSetAttribute(hmma_gemm_half,
                         cudaFuncAttributeMaxDynamicSharedMemorySize, GEMM_SMEM);
    cudaFuncSetAttribute(delta_scan,
                         cudaFuncAttributeMaxDynamicSharedMemorySize, SCAN_SMEM);

    // 0) convert inputs to fp16
    cvt_fp16<<<(MROWS * Hh / 4 + 255) / 256, 256>>>(hs, hs_h, MROWS * Hh / 4);
    cvt_fp16<<<(CONV_DIM * Hh / 4 + 255) / 256, 256>>>(W_qkv, wq_h, CONV_DIM * Hh / 4);
    cvt_fp16<<<(VAL_DIM * Hh / 4 + 255) / 256, 256>>>(W_z, wz_h, VAL_DIM * Hh / 4);
    cvt_fp16<<<(Hh * VAL_DIM / 4 + 255) / 256, 256>>>(W_out, wo_h, Hh * VAL_DIM / 4);

    // 1) qkv projection
    hmma_gemm_half<<<dim3(CONV_DIM / 128, MROWS / 128), 256, GEMM_SMEM>>>(
        hs_h, wq_h, p_mixed, MROWS, CONV_DIM, Hh);
    // 2) z projection
    hmma_gemm_half<<<dim3(VAL_DIM / 128, MROWS / 128), 256, GEMM_SMEM>>>(
        hs_h, wz_h, p_z, MROWS, VAL_DIM, Hh);
    // 3) beta / g projections
    proj_ab<<<MROWS / 64, 256>>>(hs, W_b, W_a, dt_bias, A_log, p_g, p_beta);
    // 4) depthwise conv + silu
    conv_silu<<<(Bb * Ss * (CONV_DIM / 4)) / 256, 256>>>(p_mixed, conv_w, p_conv);
    // 5) gated delta-rule scan
    delta_scan<<<Bb * NVH, 256, SCAN_SMEM>>>(p_conv, p_g, p_beta, p_o);
    // 6) gated RMSNorm -> fp16
    gate_norm<<<(Bb * Ss * NVH) / 8, 256>>>(p_o, p_z, norm_w, h_h);
    // 7) output projection
    hmma_gemm_half<<<dim3(Hh / 128, MROWS / 128), 256, GEMM_SMEM>>>(
        h_h, wo_h, out, MROWS, Hh, Hh);
}

// round 15
// speedup vs baseline: 2.4606x; 2.4606x over previous
#include <cuda_runtime.h>
#include <cuda_fp16.h>
#include <math.h>
#include <stdint.h>
#include <stddef.h>

// Problem constants
#define Bb 2
#define Ss 4096
#define Hh 1024
#define NKH 8
#define NVH 16
#define DK 64
#define DV 64
#define KEY_DIM 512
#define VAL_DIM 1024
#define CONV_DIM 2048
#define KSZ 4
#define MROWS (Bb*Ss)        // 8192
#define PCH 8                // parallel chunks per (b,h)
#define CL  (Ss/PCH)         // 512 steps per chunk
#define NBH (Bb*NVH)         // 32

// ------------------------- scratch (static device memory) -------------------
__device__ float g_mixed[(size_t)Bb*Ss*CONV_DIM];
__device__ float g_conv [(size_t)Bb*Ss*CONV_DIM];
__device__ float g_z    [(size_t)Bb*Ss*VAL_DIM];
__device__ float g_g    [(size_t)Bb*Ss*NVH];
__device__ float g_beta [(size_t)Bb*Ss*NVH];
__device__ float g_o    [(size_t)Bb*Ss*VAL_DIM];
// chunked-scan intermediates: [NBH*PCH][64][64]
__device__ float g_Sc [(size_t)NBH*PCH*64*64];   // N_c  (zero-init final state)
__device__ float g_Mc [(size_t)NBH*PCH*64*64];   // M_c  (propagator)
__device__ float g_Si [(size_t)NBH*PCH*64*64];   // S_in per chunk

// fp16 operands
__device__ __half g_hs_h  [(size_t)MROWS*Hh];
__device__ __half g_wqkv_h[(size_t)CONV_DIM*Hh];
__device__ __half g_wz_h  [(size_t)VAL_DIM*Hh];
__device__ __half g_wo_h  [(size_t)Hh*VAL_DIM];
__device__ __half g_h_h   [(size_t)MROWS*VAL_DIM];

// ========================= helpers ==========================================
__device__ __forceinline__ uint32_t smem_u32(const void* p) {
    uint32_t a;
    asm("{ .reg .u64 t; cvta.to.shared.u64 t, %1; cvt.u32.u64 %0, t; }"
        : "=r"(a) : "l"(p));
    return a;
}

#define LDSM4(r0, r1, r2, r3, addr) \
    asm volatile("ldmatrix.sync.aligned.m8n8.x4.shared.b16 {%0,%1,%2,%3}, [%4];" \
                 : "=r"(r0), "=r"(r1), "=r"(r2), "=r"(r3) : "r"(addr))

#define MMA16816(d, a, b0, b1) \
    asm volatile("mma.sync.aligned.m16n8k16.row.col.f32.f16.f16.f32 " \
                 "{%0,%1,%2,%3},{%4,%5,%6,%7},{%8,%9},{%0,%1,%2,%3};" \
                 : "+f"((d)[0]), "+f"((d)[1]), "+f"((d)[2]), "+f"((d)[3]) \
                 : "r"((a)[0]), "r"((a)[1]), "r"((a)[2]), "r"((a)[3]), \
                   "r"(b0), "r"(b1))

#define CP_ASYNC16(dst, src) \
    asm volatile("cp.async.cg.shared.global [%0], [%1], 16;" \
                 :: "r"(dst), "l"(src))
#define CP_ASYNC4(dst, src) \
    asm volatile("cp.async.ca.shared.global [%0], [%1], 4;" \
                 :: "r"(dst), "l"(src))
#define CP_COMMIT() asm volatile("cp.async.commit_group;" ::: "memory")
#define CP_WAIT2()  asm volatile("cp.async.wait_group 2;" ::: "memory")
#define CP_WAIT1()  asm volatile("cp.async.wait_group 1;" ::: "memory")

// ------------------ fp32 -> fp16 (elementwise) ------------------------------
__global__ __launch_bounds__(256) void cvt_fp16(const float* __restrict__ x,
                                                __half* __restrict__ hi,
                                                int n4) {
    int i = blockIdx.x * blockDim.x + threadIdx.x;
    if (i >= n4) return;
    float4 v = ((const float4*)x)[i];
    __half2 p0 = __floats2half2_rn(v.x, v.y);
    __half2 p1 = __floats2half2_rn(v.z, v.w);
    ((uint2*)hi)[i] = make_uint2(*(uint32_t*)&p0, *(uint32_t*)&p1);
}

// ===================== fp16 HMMA GEMM: C = A * B^T (exact R10) ==============
#define ARR_B 8192
#define STG_BYTES (2 * ARR_B)              // 16384: A, B
#define GEMM_SMEM (4 * STG_BYTES)          // 65536

__global__ __launch_bounds__(256, 2) void hmma_gemm_half(
        const __half* __restrict__ A, const __half* __restrict__ B,
        float* __restrict__ C, int M, int N, int K) {
    extern __shared__ char dynsmem[];
    const uint32_t sbase = smem_u32(dynsmem);

    const int tid  = threadIdx.x;
    const int lane = tid & 31;
    const int wid  = tid >> 5;
    const int wm   = wid & 3;
    const int wn   = wid >> 2;
    const int brow = blockIdx.y * 128;
    const int bcol = blockIdx.x * 128;

    const uint32_t aRow = (uint32_t)(wm * 32 + (lane & 15));
    const uint32_t aKq  = (uint32_t)(lane >> 4);
    const uint32_t bRow = (uint32_t)(wn * 64 + (lane & 7) + ((lane >> 4) << 3));
    const uint32_t bKq  = (uint32_t)((lane >> 3) & 1);

    float acc[2][8][4];
#pragma unroll
    for (int i = 0; i < 2; i++)
#pragma unroll
        for (int j = 0; j < 8; j++)
#pragma unroll
            for (int c = 0; c < 4; c++) acc[i][j][c] = 0.f;

    const int NK = K / 32;

#define ISSUE_STAGE(s) do { \
    uint32_t buf = sbase + (uint32_t)(((s) & 3) * STG_BYTES); \
    int k0 = (s) * 32; \
    _Pragma("unroll") \
    for (int j = 0; j < 4; j++) { \
        const int arr = j >> 1; \
        int idx = tid + (j & 1) * 256; \
        int row = idx >> 2; \
        int quad = tid & 3; \
        uint32_t sw = (uint32_t)((row << 6) + (((quad ^ ((row >> 1) & 3))) << 4)); \
        size_t so = (size_t)(((arr == 0) ? brow : bcol) + row) * K + k0 + quad * 8; \
        const __half* src = (arr == 0) ? A : B; \
        CP_ASYNC16(buf + arr * ARR_B + sw, src + so); \
    } \
    CP_COMMIT(); \
} while (0)

    ISSUE_STAGE(0);
    ISSUE_STAGE(1);
    ISSUE_STAGE(2);

    for (int s = 0; s < NK; s++) {
        CP_WAIT2();
        __syncthreads();
        if (s + 3 < NK) ISSUE_STAGE(s + 3);
        else CP_COMMIT();

        const uint32_t stg = sbase + (uint32_t)((s & 3) * STG_BYTES);
#pragma unroll
        for (int kh = 0; kh < 2; kh++) {
            const uint32_t kqb = (uint32_t)(kh * 2);
            uint32_t ah[2][4], bh[8][2];
#pragma unroll
            for (int mi = 0; mi < 2; mi++) {
                uint32_t r  = aRow + mi * 16;
                uint32_t qd = aKq + kqb;
                uint32_t ad = stg + (r << 6) + ((qd ^ ((r >> 1) & 3)) << 4);
                LDSM4(ah[mi][0], ah[mi][1], ah[mi][2], ah[mi][3], ad);
            }
#pragma unroll
            for (int g = 0; g < 4; g++) {
                uint32_t r  = bRow + g * 16;
                uint32_t qd = bKq + kqb;
                uint32_t bd = stg + ARR_B + (r << 6) + ((qd ^ ((r >> 1) & 3)) << 4);
                LDSM4(bh[g*2][0], bh[g*2][1], bh[g*2+1][0], bh[g*2+1][1], bd);
            }
#pragma unroll
            for (int mi = 0; mi < 2; mi++)
#pragma unroll
                for (int nf = 0; nf < 8; nf++)
                    MMA16816(acc[mi][nf], ah[mi], bh[nf][0], bh[nf][1]);
        }
    }

#pragma unroll
    for (int mi = 0; mi < 2; mi++) {
        int r0 = brow + wm * 32 + mi * 16 + (lane >> 2);
#pragma unroll
        for (int nf = 0; nf < 8; nf++) {
            int c = bcol + wn * 64 + nf * 8 + (lane & 3) * 2;
            *(float2*)&C[(size_t)r0 * N + c] =
                make_float2(acc[mi][nf][0], acc[mi][nf][1]);
            *(float2*)&C[(size_t)(r0 + 8) * N + c] =
                make_float2(acc[mi][nf][2], acc[mi][nf][3]);
        }
    }
#undef ISSUE_STAGE
}

// ------------------- beta / g projections (N=32 skinny GEMM) ----------------
__global__ __launch_bounds__(256) void proj_ab(const float* __restrict__ hs,
                                               const float* __restrict__ Wb,
                                               const float* __restrict__ Wa,
                                               const float* __restrict__ dt_bias,
                                               const float* __restrict__ A_log,
                                               float* __restrict__ gout,
                                               float* __restrict__ bout) {
    __shared__ float As[64][32];
    __shared__ float Ws[32][32];
    const int tid = threadIdx.x;
    const int row0 = blockIdx.x * 64;
    const int ty = tid >> 5;
    const int tx = tid & 31;

    float acc[8];
#pragma unroll
    for (int i = 0; i < 8; i++) acc[i] = 0.f;

    const int ar = tid >> 2;
    const int ak = (tid & 3) * 8;

    for (int k0 = 0; k0 < Hh; k0 += 32) {
        float4 a0 = *(const float4*)(hs + (size_t)(row0 + ar) * Hh + k0 + ak);
        float4 a1 = *(const float4*)(hs + (size_t)(row0 + ar) * Hh + k0 + ak + 4);
        As[ar][ak + 0] = a0.x; As[ar][ak + 1] = a0.y; As[ar][ak + 2] = a0.z; As[ar][ak + 3] = a0.w;
        As[ar][ak + 4] = a1.x; As[ar][ak + 5] = a1.y; As[ar][ak + 6] = a1.z; As[ar][ak + 7] = a1.w;
#pragma unroll
        for (int i = tid; i < 1024; i += 256) {
            int n = i >> 5, kk = i & 31;
            float w = (n < 16) ? Wb[(size_t)n * Hh + k0 + kk]
                               : Wa[(size_t)(n - 16) * Hh + k0 + kk];
            Ws[kk][n] = w;
        }
        __syncthreads();
#pragma unroll
        for (int kk = 0; kk < 32; kk++) {
            float w = Ws[kk][tx];
#pragma unroll
            for (int i = 0; i < 8; i++) acc[i] += As[ty * 8 + i][kk] * w;
        }
        __syncthreads();
    }

    if (tx < 16) {
#pragma unroll
        for (int i = 0; i < 8; i++) {
            int row = row0 + ty * 8 + i;
            bout[(size_t)row * NVH + tx] = 1.f / (1.f + expf(-acc[i]));
        }
    } else {
        int hh = tx - 16;
        float al = expf(A_log[hh]);
        float db = dt_bias[hh];
#pragma unroll
        for (int i = 0; i < 8; i++) {
            int row = row0 + ty * 8 + i;
            float x = acc[i] + db;
            float sp = (x > 20.f) ? x : log1pf(expf(x));
            gout[(size_t)row * NVH + hh] = -al * sp;
        }
    }
}

// ------------------------- depthwise causal conv + silu ---------------------
__global__ __launch_bounds__(256) void conv_silu(const float* __restrict__ x,
                                                 const float* __restrict__ w,
                                                 float* __restrict__ y) {
    const int C4 = CONV_DIM / 4;
    int idx = blockIdx.x * blockDim.x + threadIdx.x;
    int c4 = idx & (C4 - 1);
    int s  = (idx >> 9) & (Ss - 1);
    int b  = idx >> 21;

    float4 t0 = ((const float4*)w)[c4 * 4 + 0];
    float4 t1 = ((const float4*)w)[c4 * 4 + 1];
    float4 t2 = ((const float4*)w)[c4 * 4 + 2];
    float4 t3 = ((const float4*)w)[c4 * 4 + 3];

    float a0 = 0.f, a1 = 0.f, a2 = 0.f, a3 = 0.f;
#pragma unroll
    for (int j = 0; j < KSZ; j++) {
        int st = s - (KSZ - 1) + j;
        if (st < 0) continue;
        float4 xv = ((const float4*)x)[((size_t)b * Ss + st) * C4 + c4];
        float w0 = (j == 0) ? t0.x : (j == 1) ? t0.y : (j == 2) ? t0.z : t0.w;
        float w1 = (j == 0) ? t1.x : (j == 1) ? t1.y : (j == 2) ? t1.z : t1.w;
        float w2 = (j == 0) ? t2.x : (j == 1) ? t2.y : (j == 2) ? t2.z : t2.w;
        float w3 = (j == 0) ? t3.x : (j == 1) ? t3.y : (j == 2) ? t3.z : t3.w;
        a0 += w0 * xv.x; a1 += w1 * xv.y; a2 += w2 * xv.z; a3 += w3 * xv.w;
    }
    float4 out;
    out.x = a0 / (1.f + expf(-a0));
    out.y = a1 / (1.f + expf(-a1));
    out.z = a2 / (1.f + expf(-a2));
    out.w = a3 / (1.f + expf(-a3));
    ((float4*)y)[((size_t)b * Ss + s) * C4 + c4] = out;
}

// =================== chunked-parallel gated delta-rule scan ==================
// S_t = A_t S_{t-1} + b_t,  A_t = dec_t (I - beta_t k_t k_t^T).
// Phase1: per chunk, from S=0 compute N_c (final state) and M_c = prod A_t.
// Phase2: S_in[c+1] = M_c S_in[c] + N_c   (sequential over PCH chunks).
// Phase3: per chunk, scan from S_in[c], emit outputs.
#define CHNK 32

// ---- phase 1: k,v staging only ----
#define P1_TFLOATS (2*CHNK*64 + 2*CHNK)
#define P1_SMEM (2*P1_TFLOATS*4)

__global__ __launch_bounds__(256) void scan_p1(const float* __restrict__ conv,
                                               const float* __restrict__ gg,
                                               const float* __restrict__ bb_,
                                               float* __restrict__ Sc,
                                               float* __restrict__ Mc) {
    extern __shared__ float ss[];
    const int tid  = threadIdx.x;
    const int lane = tid & 31;
    const int warp = tid >> 5;
    const int bhc = blockIdx.x;
    const int bh  = bhc >> 3;
    const int cch = bhc & 7;
    const int b = bh >> 4, h = bh & 15;

    const int v  = warp * 8 + (lane >> 2);
    const int kb = (lane & 3) * 16;

    const int koff = KEY_DIM + (h >> 1) * DK;
    const int voff = 2 * KEY_DIM + h * DV;
    const int offs2[2] = {koff, voff};

    float S0r[8], S1r[8], M0r[8], M1r[8];
#pragma unroll
    for (int i = 0; i < 8; i++) {
        S0r[i] = 0.f; S1r[i] = 0.f;
        M0r[i] = ((kb + i) == v) ? 1.f : 0.f;
        M1r[i] = ((kb + 8 + i) == v) ? 1.f : 0.f;
    }

#define ISSUE_P1(cbase, dstf) do { \
    float* _d = (dstf); \
    for (int i = tid; i < CHNK * 32; i += 256) { \
        int t = i >> 5; int r = i & 31; int tensor = r >> 4; int seg = r & 15; \
        size_t row = ((size_t)b * Ss + (cbase) + t) * CONV_DIM; \
        CP_ASYNC16(smem_u32(_d + tensor * (CHNK*64) + t * 64 + seg * 4), \
                   conv + row + offs2[tensor] + seg * 4); \
    } \
    if (tid < CHNK) { \
        size_t r = ((size_t)b * Ss + (cbase) + tid) * NVH + h; \
        CP_ASYNC4(smem_u32(_d + 2*CHNK*64 + tid), gg + r); \
        CP_ASYNC4(smem_u32(_d + 2*CHNK*64 + CHNK + tid), bb_ + r); \
    } \
    CP_COMMIT(); \
} while (0)

    const int base0 = cch * CL;
    ISSUE_P1(base0, ss);

    const int NCc = CL / CHNK;                  // 16
    for (int c = 0; c < NCc; c++) {
        const int p = c & 1;
        __syncthreads();
        if (c + 1 < NCc) ISSUE_P1(base0 + (c + 1) * CHNK, ss + (p ^ 1) * P1_TFLOATS);
        else CP_COMMIT();
        CP_WAIT1();
        __syncthreads();

        const float* tk = ss + p * P1_TFLOATS;
        const float* tv = tk + CHNK * 64;
        const float* tg = tv + CHNK * 64;
        const float* tb = tg + CHNK;

        for (int t = 0; t < CHNK; t++) {
            float4 k0 = *(const float4*)(tk + t * 64 + kb + 0);
            float4 k1 = *(const float4*)(tk + t * 64 + kb + 4);
            float4 k2 = *(const float4*)(tk + t * 64 + kb + 8);
            float4 k3 = *(const float4*)(tk + t * 64 + kb + 12);
            float vt  = tv[t * 64 + v];
            float dec = __expf(tg[t]);
            float bt  = tb[t];
            float kr[16] = {k0.x,k0.y,k0.z,k0.w, k1.x,k1.y,k1.z,k1.w,
                            k2.x,k2.y,k2.z,k2.w, k3.x,k3.y,k3.z,k3.w};

            float a0=0.f, a1=0.f, a2=0.f, a3=0.f;   // kv partials (S)
            float m0=0.f, m1=0.f, m2=0.f, m3=0.f;   // pm partials (M)
#pragma unroll
            for (int i = 0; i < 4; i++) {
                S0r[i]     *= dec;  a0 += S0r[i]     * kr[i];
                S0r[i + 4] *= dec;  a1 += S0r[i + 4] * kr[i + 4];
                S1r[i]     *= dec;  a2 += S1r[i]     * kr[i + 8];
                S1r[i + 4] *= dec;  a3 += S1r[i + 4] * kr[i + 12];
                M0r[i]     *= dec;  m0 += M0r[i]     * kr[i];
                M0r[i + 4] *= dec;  m1 += M0r[i + 4] * kr[i + 4];
                M1r[i]     *= dec;  m2 += M1r[i]     * kr[i + 8];
                M1r[i + 4] *= dec;  m3 += M1r[i + 4] * kr[i + 12];
            }
            float kv = (a0 + a1) + (a2 + a3);
            float pm = (m0 + m1) + (m2 + m3);
            kv += __shfl_xor_sync(0xffffffffu, kv, 1);
            pm += __shfl_xor_sync(0xffffffffu, pm, 1);
            kv += __shfl_xor_sync(0xffffffffu, kv, 2);
            pm += __shfl_xor_sync(0xffffffffu, pm, 2);
            float dS = (vt - kv) * bt;
            float dM = -pm * bt;
#pragma unroll
            for (int i = 0; i < 4; i++) {
                S0r[i]     += kr[i]      * dS;
                S0r[i + 4] += kr[i + 4]  * dS;
                S1r[i]     += kr[i + 8]  * dS;
                S1r[i + 4] += kr[i + 12] * dS;
                M0r[i]     += kr[i]      * dM;
                M0r[i + 4] += kr[i + 4]  * dM;
                M1r[i]     += kr[i + 8]  * dM;
                M1r[i + 4] += kr[i + 12] * dM;
            }
        }
    }

    const size_t sb = (size_t)bhc * 64 * 64;
#pragma unroll
    for (int i = 0; i < 8; i++) {
        Sc[sb + (size_t)(kb + i)     * 64 + v] = S0r[i];
        Sc[sb + (size_t)(kb + 8 + i) * 64 + v] = S1r[i];
        Mc[sb + (size_t)(kb + i)     * 64 + v] = M0r[i];
        Mc[sb + (size_t)(kb + 8 + i) * 64 + v] = M1r[i];
    }
#undef ISSUE_P1
}

// ---- phase 2: sequential composition over chunks ----
__global__ __launch_bounds__(256) void scan_p2(const float* __restrict__ Sc,
                                               const float* __restrict__ Mc,
                                               float* __restrict__ Si) {
    __shared__ float sh[64 * 65];
    const int tid  = threadIdx.x;
    const int lane = tid & 31;
    const int warp = tid >> 5;
    const int bh = blockIdx.x;
    const int v  = warp * 8 + (lane >> 2);
    const int kb = (lane & 3) * 16;

    float sv[64];
#pragma unroll
    for (int m = 0; m < 64; m++) sv[m] = 0.f;   // S_in[0] = 0

    for (int c = 0; c < PCH - 1; c++) {
        const size_t slot = (size_t)(bh * PCH + c) * 4096;
        float ns[16];
#pragma unroll
        for (int i = 0; i < 16; i++) {
            int r = kb + i;
            float acc = Sc[slot + (size_t)r * 64 + v];
            const float4* mr = (const float4*)(Mc + slot + (size_t)r * 64);
#pragma unroll
            for (int m4 = 0; m4 < 16; m4++) {
                float4 mv = mr[m4];
                acc += mv.x * sv[m4*4] + mv.y * sv[m4*4+1]
                     + mv.z * sv[m4*4+2] + mv.w * sv[m4*4+3];
            }
            ns[i] = acc;
        }
        const size_t ob = (size_t)(bh * PCH + c + 1) * 4096;
#pragma unroll
        for (int i = 0; i < 16; i++) {
            Si[ob + (size_t)(kb + i) * 64 + v] = ns[i];
            sh[(kb + i) * 65 + v] = ns[i];
        }
        __syncthreads();
#pragma unroll
        for (int m = 0; m < 64; m++) sv[m] = sh[m * 65 + v];
        __syncthreads();
    }
}

// ---- phase 3: scan with correct initial state, emit outputs ----
#define SCAN_TFLOATS (3*CHNK*64 + 2*CHNK)
#define SCAN_SMEM (2*SCAN_TFLOATS*4)

__global__ __launch_bounds__(256) void scan_p3(const float* __restrict__ conv,
                                               const float* __restrict__ gg,
                                               const float* __restrict__ bb_,
                                               const float* __restrict__ Si,
                                               float* __restrict__ out) {
    extern __shared__ float ss[];
    const int tid  = threadIdx.x;
    const int lane = tid & 31;
    const int warp = tid >> 5;
    const int bhc = blockIdx.x;
    const int bh  = bhc >> 3;
    const int cch = bhc & 7;
    const int b = bh >> 4, h = bh & 15;

    const int v  = warp * 8 + (lane >> 2);
    const int kb = (lane & 3) * 16;

    const int qoff = (h >> 1) * DK;
    const int koff = KEY_DIM + (h >> 1) * DK;
    const int voff = 2 * KEY_DIM + h * DV;
    const int offs[3] = {qoff, koff, voff};

    float S0r[8], S1r[8];
    if (cch == 0) {
#pragma unroll
        for (int i = 0; i < 8; i++) { S0r[i] = 0.f; S1r[i] = 0.f; }
    } else {
        const size_t sb = (size_t)bhc * 4096;
#pragma unroll
        for (int i = 0; i < 8; i++) {
            S0r[i] = Si[sb + (size_t)(kb + i)     * 64 + v];
            S1r[i] = Si[sb + (size_t)(kb + 8 + i) * 64 + v];
        }
    }

#define ISSUE_CHUNK(cbase, dstf) do { \
    float* _d = (dstf); \
    for (int i = tid; i < CHNK * 48; i += 256) { \
        int t = i / 48; int r = i - t * 48; int tensor = r >> 4; int seg = r & 15; \
        size_t row = ((size_t)b * Ss + (cbase) + t) * CONV_DIM; \
        CP_ASYNC16(smem_u32(_d + tensor * (CHNK*64) + t * 64 + seg * 4), \
                   conv + row + offs[tensor] + seg * 4); \
    } \
    if (tid < CHNK) { \
        size_t r = ((size_t)b * Ss + (cbase) + tid) * NVH + h; \
        CP_ASYNC4(smem_u32(_d + 3*CHNK*64 + tid), gg + r); \
        CP_ASYNC4(smem_u32(_d + 3*CHNK*64 + CHNK + tid), bb_ + r); \
    } \
    CP_COMMIT(); \
} while (0)

    const int base0 = cch * CL;
    ISSUE_CHUNK(base0, ss);

    const int NCc = CL / CHNK;                  // 16
    for (int c = 0; c < NCc; c++) {
        const int p = c & 1;
        __syncthreads();
        if (c + 1 < NCc) ISSUE_CHUNK(base0 + (c + 1) * CHNK, ss + (p ^ 1) * SCAN_TFLOATS);
        else CP_COMMIT();
        CP_WAIT1();
        __syncthreads();

        const float* tq = ss + p * SCAN_TFLOATS;
        const float* tk = tq + CHNK * 64;
        const float* tv = tk + CHNK * 64;
        const float* tg = tv + CHNK * 64;
        const float* tb = tg + CHNK;

        for (int t = 0; t < CHNK; t++) {
            float4 k0 = *(const float4*)(tk + t * 64 + kb + 0);
            float4 k1 = *(const float4*)(tk + t * 64 + kb + 4);
            float4 k2 = *(const float4*)(tk + t * 64 + kb + 8);
            float4 k3 = *(const float4*)(tk + t * 64 + kb + 12);
            float4 q0 = *(const float4*)(tq + t * 64 + kb + 0);
            float4 q1 = *(const float4*)(tq + t * 64 + kb + 4);
            float4 q2 = *(const float4*)(tq + t * 64 + kb + 8);
            float4 q3 = *(const float4*)(tq + t * 64 + kb + 12);
            float vt  = tv[t * 64 + v];
            float dec = __expf(tg[t]);
            float bt  = tb[t];

            float kr[16] = {k0.x,k0.y,k0.z,k0.w, k1.x,k1.y,k1.z,k1.w,
                            k2.x,k2.y,k2.z,k2.w, k3.x,k3.y,k3.z,k3.w};
            float qr[16] = {q0.x,q0.y,q0.z,q0.w, q1.x,q1.y,q1.z,q1.w,
                            q2.x,q2.y,q2.z,q2.w, q3.x,q3.y,q3.z,q3.w};

            float a0 = 0.f, a1 = 0.f, a2 = 0.f, a3 = 0.f;
#pragma unroll
            for (int i = 0; i < 4; i++) {
                S0r[i]     *= dec;  a0 += S0r[i]     * kr[i];
                S0r[i + 4] *= dec;  a1 += S0r[i + 4] * kr[i + 4];
                S1r[i]     *= dec;  a2 += S1r[i]     * kr[i + 8];
                S1r[i + 4] *= dec;  a3 += S1r[i + 4] * kr[i + 12];
            }
            float kv = (a0 + a1) + (a2 + a3);
            kv += __shfl_xor_sync(0xffffffffu, kv, 1);
            kv += __shfl_xor_sync(0xffffffffu, kv, 2);
            float delta = (vt - kv) * bt;

            float o0 = 0.f, o1 = 0.f, o2 = 0.f, o3 = 0.f;
#pragma unroll
            for (int i = 0; i < 4; i++) {
                S0r[i]     += kr[i]      * delta;  o0 += S0r[i]     * qr[i];
                S0r[i + 4] += kr[i + 4]  * delta;  o1 += S0r[i + 4] * qr[i + 4];
                S1r[i]     += kr[i + 8]  * delta;  o2 += S1r[i]     * qr[i + 8];
                S1r[i + 4] += kr[i + 12] * delta;  o3 += S1r[i + 4] * qr[i + 12];
            }
            float o = (o0 + o1) + (o2 + o3);
            o += __shfl_xor_sync(0xffffffffu, o, 1);
            o += __shfl_xor_sync(0xffffffffu, o, 2);
            if ((lane & 3) == 0)
                out[(((size_t)b * Ss + base0 + c * CHNK + t) * NVH + h) * DV + v]
                    = o * 0.125f;
        }
    }
#undef ISSUE_CHUNK
}

// -------------- gated RMSNorm (emits fp16 directly) -------------------------
__global__ __launch_bounds__(256) void gate_norm(const float* __restrict__ o,
                                                 const float* __restrict__ z,
                                                 const float* __restrict__ w,
                                                 __half* __restrict__ hh) {
    int gid  = blockIdx.x * 8 + (threadIdx.x >> 5);
    int lane = threadIdx.x & 31;
    size_t base = (size_t)gid * 64;
    float z0 = z[base + lane],      z1 = z[base + lane + 32];
    float o0 = o[base + lane],      o1 = o[base + lane + 32];
    float v0 = o0 * (z0 / (1.f + expf(-z0)));
    float v1 = o1 * (z1 / (1.f + expf(-z1)));
    float ss = v0 * v0 + v1 * v1;
#pragma unroll
    for (int m = 16; m; m >>= 1) ss += __shfl_xor_sync(0xffffffffu, ss, m);
    float scale = rsqrtf(ss * (1.f / 64.f) + 1e-6f);
    hh[base + lane]      = __float2half_rn(v0 * scale * w[lane]);
    hh[base + lane + 32] = __float2half_rn(v1 * scale * w[lane + 32]);
}

// ------------------------- launcher -----------------------------------------
extern "C" void kernel_launch(void* const* d_in, const int* in_sizes, int n_in,
                              void* d_out, int out_size) {
    const float* hs       = (const float*)d_in[0];
    const float* W_qkv    = (const float*)d_in[1];
    const float* conv_w   = (const float*)d_in[2];
    const float* W_z      = (const float*)d_in[3];
    const float* W_b      = (const float*)d_in[4];
    const float* W_a      = (const float*)d_in[5];
    const float* dt_bias  = (const float*)d_in[6];
    const float* A_log    = (const float*)d_in[7];
    const float* norm_w   = (const float*)d_in[8];
    const float* W_out    = (const float*)d_in[9];
    float* out = (float*)d_out;

    float *p_mixed, *p_conv, *p_z, *p_g, *p_beta, *p_o, *p_Sc, *p_Mc, *p_Si;
    __half *hs_h, *wq_h, *wz_h, *wo_h, *h_h;
    cudaGetSymbolAddress((void**)&p_mixed, g_mixed);
    cudaGetSymbolAddress((void**)&p_conv,  g_conv);
    cudaGetSymbolAddress((void**)&p_z,     g_z);
    cudaGetSymbolAddress((void**)&p_g,     g_g);
    cudaGetSymbolAddress((void**)&p_beta,  g_beta);
    cudaGetSymbolAddress((void**)&p_o,     g_o);
    cudaGetSymbolAddress((void**)&p_Sc,    g_Sc);
    cudaGetSymbolAddress((void**)&p_Mc,    g_Mc);
    cudaGetSymbolAddress((void**)&p_Si,    g_Si);
    cudaGetSymbolAddress((void**)&hs_h,    g_hs_h);
    cudaGetSymbolAddress((void**)&wq_h,    g_wqkv_h);
    cudaGetSymbolAddress((void**)&wz_h,    g_wz_h);
    cudaGetSymbolAddress((void**)&wo_h,    g_wo_h);
    cudaGetSymbolAddress((void**)&h_h,     g_h_h);

    cudaFuncSetAttribute(hmma_gemm_half,
                         cudaFuncAttributeMaxDynamicSharedMemorySize, GEMM_SMEM);
    cudaFuncSetAttribute(scan_p3,
                         cudaFuncAttributeMaxDynamicSharedMemorySize, SCAN_SMEM);

    // 0) convert inputs to fp16
    cvt_fp16<<<(MROWS * Hh / 4 + 255) / 256, 256>>>(hs, hs_h, MROWS * Hh / 4);
    cvt_fp16<<<(CONV_DIM * Hh / 4 + 255) / 256, 256>>>(W_qkv, wq_h, CONV_DIM * Hh / 4);
    cvt_fp16<<<(VAL_DIM * Hh / 4 + 255) / 256, 256>>>(W_z, wz_h, VAL_DIM * Hh / 4);
    cvt_fp16<<<(Hh * VAL_DIM / 4 + 255) / 256, 256>>>(W_out, wo_h, Hh * VAL_DIM / 4);

    // 1) qkv projection
    hmma_gemm_half<<<dim3(CONV_DIM / 128, MROWS / 128), 256, GEMM_SMEM>>>(
        hs_h, wq_h, p_mixed, MROWS, CONV_DIM, Hh);
    // 2) z projection
    hmma_gemm_half<<<dim3(VAL_DIM / 128, MROWS / 128), 256, GEMM_SMEM>>>(
        hs_h, wz_h, p_z, MROWS, VAL_DIM, Hh);
    // 3) beta / g projections
    proj_ab<<<MROWS / 64, 256>>>(hs, W_b, W_a, dt_bias, A_log, p_g, p_beta);
    // 4) depthwise conv + silu
    conv_silu<<<(Bb * Ss * (CONV_DIM / 4)) / 256, 256>>>(p_mixed, conv_w, p_conv);
    // 5) chunked-parallel gated delta-rule scan
    scan_p1<<<NBH * PCH, 256, P1_SMEM>>>(p_conv, p_g, p_beta, p_Sc, p_Mc);
    scan_p2<<<NBH, 256>>>(p_Sc, p_Mc, p_Si);
    scan_p3<<<NBH * PCH, 256, SCAN_SMEM>>>(p_conv, p_g, p_beta, p_Si, p_o);
    // 6) gated RMSNorm -> fp16
    gate_norm<<<(Bb * Ss * NVH) / 8, 256>>>(p_o, p_z, norm_w, h_h);
    // 7) output projection
    hmma_gemm_half<<<dim3(Hh / 128, MROWS / 128), 256, GEMM_SMEM>>>(
        h_h, wo_h, out, MROWS, Hh, Hh);
}